// round 6
// baseline (speedup 1.0000x reference)
#include <cuda_runtime.h>
#include <cstdint>

// ---------------------------------------------------------------------------
// Q[n,m] = P[n] + R[m] + sum_h (w2[h]/2) * |a[n,h] + b[m,h]|
//   (relu(x) = (x+|x|)/2 ; rank-1 halves folded into per-row P/R)
// Inner loop: packed f32x2 add + fma, |.| folded as FFMA2 operand modifier.
// 128 threads, 64x64 tile, 8n x 4m per thread, 3 CTAs/SM with explicit
// double-buffered register prefetch across the h2 loop.
// ---------------------------------------------------------------------------

#define NMAX 2048
#define HID  64
#define HP   32   // h pairs

__device__ unsigned long long g_aT[HP][NMAX];  // pack(a[n][2h2], a[n][2h2+1])
__device__ unsigned long long g_bT[HP][NMAX];  // pack(b[m][2h2], b[m][2h2+1])
__device__ float g_P[NMAX];
__device__ float g_R[NMAX];

__device__ __forceinline__ unsigned long long pack2(float lo, float hi) {
    return (unsigned long long)__float_as_uint(lo) |
           ((unsigned long long)__float_as_uint(hi) << 32);
}

// ---------------------------------------------------------------------------
// Precompute: one warp per row; lane = h-pair. Warp-shuffle rank-1 reduce.
// ---------------------------------------------------------------------------
__global__ void __launch_bounds__(256) precompute_kernel(
    const float* __restrict__ job, const float* __restrict__ mac,
    const float* __restrict__ gvec,
    const float* __restrict__ Wj, const float* __restrict__ bj,
    const float* __restrict__ Wm, const float* __restrict__ bm,
    const float* __restrict__ Wg, const float* __restrict__ bg,
    const float* __restrict__ W1, const float* __restrict__ b1,
    const float* __restrict__ W2, const float* __restrict__ b2,
    int n, int m)
{
    const int row  = blockIdx.x * 8 + (threadIdx.x >> 5);
    const int lane = threadIdx.x & 31;
    if (row >= n + m) return;

    float2 w2p = *(const float2*)&W2[2 * lane];

    if (row < n) {
        const float x = job[row];
        float h0 = 0.0f, h1 = 0.0f;
        #pragma unroll
        for (int j = 0; j < 16; ++j) {
            float f = fmaxf(fmaf(x, Wj[j], bj[j]), 0.0f);
            float2 w = *(const float2*)&W1[j * HID + 2 * lane];
            h0 = fmaf(f, w.x, h0);
            h1 = fmaf(f, w.y, h1);
        }
        g_aT[lane][row] = pack2(h0, h1);
        float s = h0 * w2p.x + h1 * w2p.y;
        #pragma unroll
        for (int d = 16; d > 0; d >>= 1)
            s += __shfl_xor_sync(0xFFFFFFFFu, s, d);
        if (lane == 0) g_P[row] = 0.5f * s + b2[0];
    } else {
        const int mm = row - n;
        const float x = mac[mm];
        float2 bb = *(const float2*)&b1[2 * lane];
        float h0 = bb.x, h1 = bb.y;
        #pragma unroll
        for (int k = 0; k < 8; ++k) {
            float gf = bg[k];
            #pragma unroll
            for (int i = 0; i < 8; ++i)
                gf = fmaf(gvec[i], Wg[i * 8 + k], gf);
            gf = fmaxf(gf, 0.0f);
            float2 w = *(const float2*)&W1[(32 + k) * HID + 2 * lane];
            h0 = fmaf(gf, w.x, h0);
            h1 = fmaf(gf, w.y, h1);
        }
        #pragma unroll
        for (int j = 0; j < 16; ++j) {
            float f = fmaxf(fmaf(x, Wm[j], bm[j]), 0.0f);
            float2 w = *(const float2*)&W1[(16 + j) * HID + 2 * lane];
            h0 = fmaf(f, w.x, h0);
            h1 = fmaf(f, w.y, h1);
        }
        g_bT[lane][mm] = pack2(h0, h1);
        float s = h0 * w2p.x + h1 * w2p.y;
        #pragma unroll
        for (int d = 16; d > 0; d >>= 1)
            s += __shfl_xor_sync(0xFFFFFFFFu, s, d);
        if (lane == 0) g_R[mm] = 0.5f * s;
    }
}

// ---------------------------------------------------------------------------
// Core step: acc(f32x2) += |a + b| * w   (w pre-scaled by 0.5)
// ---------------------------------------------------------------------------
__device__ __forceinline__ void step(unsigned long long& acc,
                                     unsigned long long a,
                                     unsigned long long b,
                                     unsigned long long w)
{
    asm("{\n\t"
        ".reg .b64 t;\n\t"
        ".reg .f32 lo, hi;\n\t"
        "add.rn.f32x2 t, %1, %2;\n\t"
        "mov.b64 {lo, hi}, t;\n\t"
        "abs.f32 lo, lo;\n\t"
        "abs.f32 hi, hi;\n\t"
        "mov.b64 t, {lo, hi};\n\t"
        "fma.rn.f32x2 %0, t, %3, %0;\n\t"
        "}"
        : "+l"(acc)
        : "l"(a), "l"(b), "l"(w));
}

// ---------------------------------------------------------------------------
// Main kernel: 128 threads, 64x64 tile, 8n x 4m per thread, 3 CTAs/SM.
// Double-buffered register prefetch across h2 iterations.
// ---------------------------------------------------------------------------
__global__ void __launch_bounds__(128, 3) qmain_kernel(
    const float* __restrict__ W2,
    float* __restrict__ out, int N, int M)
{
    __shared__ unsigned long long sA[HP][64];   // 16 KB
    __shared__ unsigned long long sB[HP][64];   // 16 KB
    __shared__ unsigned long long sW[HP];       // 256 B (0.5*w2 pairs)
    __shared__ float sP[64];
    __shared__ float sR[64];

    const int tid = threadIdx.x;
    const int nBase = blockIdx.y * 64;
    const int mBase = blockIdx.x * 64;

    if (tid < HP) {
        float2 w = *(const float2*)&W2[2 * tid];
        sW[tid] = pack2(0.5f * w.x, 0.5f * w.y);
    }
    if (tid < 64) sP[tid] = g_P[nBase + tid];
    else          sR[tid - 64] = g_R[mBase + (tid - 64)];

    #pragma unroll
    for (int i = 0; i < 16; ++i) {
        int idx = tid + i * 128;
        int h2 = idx >> 6, l = idx & 63;
        sA[h2][l] = g_aT[h2][nBase + l];
        sB[h2][l] = g_bT[h2][mBase + l];
    }
    __syncthreads();

    const int tx = tid & 15;        // m: 16 cols x 4
    const int ty = tid >> 4;        // n: 8 rows x 8
    const int n0 = ty * 8;
    const int m0 = tx * 4;

    unsigned long long acc[8][4];
    #pragma unroll
    for (int i = 0; i < 8; ++i)
        #pragma unroll
        for (int j = 0; j < 4; ++j)
            acc[i][j] = 0ull;

    // --- software pipeline over h2: prefetch next batch, then compute ---
    unsigned long long A[8], B[4], w;
    {
        ulonglong2 a0 = *(const ulonglong2*)&sA[0][n0 + 0];
        ulonglong2 a1 = *(const ulonglong2*)&sA[0][n0 + 2];
        ulonglong2 a2 = *(const ulonglong2*)&sA[0][n0 + 4];
        ulonglong2 a3 = *(const ulonglong2*)&sA[0][n0 + 6];
        ulonglong2 b0 = *(const ulonglong2*)&sB[0][m0 + 0];
        ulonglong2 b1 = *(const ulonglong2*)&sB[0][m0 + 2];
        A[0]=a0.x; A[1]=a0.y; A[2]=a1.x; A[3]=a1.y;
        A[4]=a2.x; A[5]=a2.y; A[6]=a3.x; A[7]=a3.y;
        B[0]=b0.x; B[1]=b0.y; B[2]=b1.x; B[3]=b1.y;
        w = sW[0];
    }

    #pragma unroll 4
    for (int h2 = 0; h2 < HP; ++h2) {
        // Prefetch batch for h2+1 (masked: last iteration reloads h2=0, unused).
        const int hn = (h2 + 1) & (HP - 1);
        ulonglong2 a0 = *(const ulonglong2*)&sA[hn][n0 + 0];
        ulonglong2 a1 = *(const ulonglong2*)&sA[hn][n0 + 2];
        ulonglong2 a2 = *(const ulonglong2*)&sA[hn][n0 + 4];
        ulonglong2 a3 = *(const ulonglong2*)&sA[hn][n0 + 6];
        ulonglong2 b0 = *(const ulonglong2*)&sB[hn][m0 + 0];
        ulonglong2 b1 = *(const ulonglong2*)&sB[hn][m0 + 2];
        unsigned long long wn = sW[hn];

        #pragma unroll
        for (int i = 0; i < 8; ++i)
            #pragma unroll
            for (int j = 0; j < 4; ++j)
                step(acc[i][j], A[i], B[j], w);

        A[0]=a0.x; A[1]=a0.y; A[2]=a1.x; A[3]=a1.y;
        A[4]=a2.x; A[5]=a2.y; A[6]=a3.x; A[7]=a3.y;
        B[0]=b0.x; B[1]=b0.y; B[2]=b1.x; B[3]=b1.y;
        w = wn;
    }

    // Epilogue: r = acc.lo + acc.hi + P[n] + R[m]
    #pragma unroll
    for (int i = 0; i < 8; ++i) {
        const float pn = sP[n0 + i];
        float r[4];
        #pragma unroll
        for (int j = 0; j < 4; ++j) {
            unsigned long long u = acc[i][j];
            r[j] = (__uint_as_float((unsigned)u) +
                    __uint_as_float((unsigned)(u >> 32))) + (pn + sR[m0 + j]);
        }
        float4 v = make_float4(r[0], r[1], r[2], r[3]);
        *(float4*)&out[(size_t)(nBase + n0 + i) * M + (mBase + m0)] = v;
    }
}

// ---------------------------------------------------------------------------
// Launch
// ---------------------------------------------------------------------------
extern "C" void kernel_launch(void* const* d_in, const int* in_sizes, int n_in,
                              void* d_out, int out_size)
{
    const float* job  = (const float*)d_in[0];
    const float* mac  = (const float*)d_in[1];
    const float* gvec = (const float*)d_in[2];
    const float* Wj   = (const float*)d_in[3];
    const float* bj   = (const float*)d_in[4];
    const float* Wm   = (const float*)d_in[5];
    const float* bm   = (const float*)d_in[6];
    const float* Wg   = (const float*)d_in[7];
    const float* bg   = (const float*)d_in[8];
    const float* W1   = (const float*)d_in[9];
    const float* b1   = (const float*)d_in[10];
    const float* W2   = (const float*)d_in[11];
    const float* b2   = (const float*)d_in[12];
    float* out = (float*)d_out;

    const int N = in_sizes[0];
    const int M = in_sizes[1];

    int rows = N + M;
    precompute_kernel<<<(rows + 7) / 8, 256>>>(
        job, mac, gvec, Wj, bj, Wm, bm, Wg, bg, W1, b1, W2, b2, N, M);

    dim3 grid(M / 64, N / 64);
    qmain_kernel<<<grid, 128>>>(W2, out, N, M);
}